// round 15
// baseline (speedup 1.0000x reference)
#include <cuda_runtime.h>
#include <math.h>
#include <stdint.h>
#include <mma.h>
using namespace nvcuda;

#define B_   128
#define T_   512
#define F_   512
#define U_   256
#define NROW 65536        // T*B
#define NB   256          // 2*B (fwd+bwd batched)
#define RING 8
#define RSZ  (NB * U_)    // 65536
#define NCTA 128          // persistent grid <= SM count => co-resident
#define BK   16           // tgemm K-tile

// ---------------- scratch (__device__ globals; no allocation allowed) ---------
__device__ float g_xT [(size_t)NROW * F_];
__device__ float g_xg [(size_t)NROW * 1024];
__device__ float g_xh [(size_t)NROW * U_];
__device__ float g_xc [(size_t)NROW * U_];
__device__ float g_outs[(size_t)NROW * 512];
__device__ float g_c1 [(size_t)NROW * U_];
__device__ float g_c2 [(size_t)NROW * U_];
__device__ float g_H   [RING * RSZ];
__device__ float g_C   [RING * RSZ];
__device__ float g_QH  [RING * RSZ];     // h_k @ Wh_state
__device__ float g_QC  [RING * RSZ];     // c_k @ Wc_state
__device__ float g_QC4H[RING * RSZ];     // c_k @ Wh_state (4th c-slot uses Wh)
__device__ float g_hmix[NB * U_];
__device__ float g_cmix[NB * U_];
__device__ float4 g_rk4 [U_ * U_];       // rk: [k][j] -> (i,f,m,o)
__device__ float2 g_att2[U_ * U_];       // [k][j] -> (Wh_state, Wc_state)
__device__ unsigned g_count;             // cumulative barrier counter

__device__ __forceinline__ float hsig(float x) {
    return fminf(fmaxf(0.2f * x + 0.5f, 0.f), 1.f);
}

// ---------------- per-launch init ---------------------------------------------
__global__ void k_zero() {
    int i = blockIdx.x * blockDim.x + threadIdx.x;
    if (i < RING * RSZ) {
        g_H[i] = 0.f; g_C[i] = 0.f;
        g_QH[i] = 0.f; g_QC[i] = 0.f; g_QC4H[i] = 0.f;
    }
    if (i == 0) g_count = 0u;
}

// ---------------- permute x (b,t,f) -> (t,b,f) --------------------------------
__global__ void k_permute(const float* __restrict__ x) {
    int r = blockIdx.x;                 // r = t*128 + b
    int t = r >> 7, b = r & 127;
    const float4* src = (const float4*)(x + ((size_t)b * T_ + t) * F_);
    float4* dst = (float4*)(g_xT + (size_t)r * F_);
    dst[threadIdx.x] = src[threadIdx.x];
}

// ---------------- weight prep --------------------------------------------------
__global__ void k_prep_rk(const float* __restrict__ rk) {
    int k = blockIdx.x, j = threadIdx.x;
    g_rk4[k * U_ + j] = make_float4(rk[k * 1024 + j],
                                    rk[k * 1024 + 256 + j],
                                    rk[k * 1024 + 512 + j],
                                    rk[k * 1024 + 768 + j]);
}
__global__ void k_prep_att(const float* __restrict__ att_h, const float* __restrict__ att_c) {
    int k = blockIdx.x, j = threadIdx.x;
    g_att2[k * U_ + j] = make_float2(att_h[k * U_ + j], att_c[k * U_ + j]);
}

// ---------------- tensor-core GEMM: tf32 compensated, split ONCE at staging ---
// C[M,N] = A[M,K] @ W[K,N], row-major. Staging splits v = hi + lo (tf32 each);
// inner loop is pure fragment loads + 3 MMAs: hi*hi + hi*lo + lo*hi.
// CTA 128x128, 8 warps (4x2), warp tile 32x64 (2x4 m16n16k8 tf32 tiles).
__global__ void __launch_bounds__(256)
k_tgemm(const float* __restrict__ A, const float* __restrict__ W,
        float* __restrict__ C, int M, int N, int K, int lda, int ldw) {
    __shared__ float Ah[128][BK + 4], Al[128][BK + 4];
    __shared__ float Bh[BK][128 + 4], Bl[BK][128 + 4];
    const int tid = threadIdx.x, wid = tid >> 5;
    const int bm = blockIdx.y, bn = blockIdx.x;
    const int wr = wid >> 1, wc = wid & 1;           // 4x2 warp layout
    const float* Ab = A + (size_t)(bm * 128) * lda;
    const float* Wb = W + bn * 128;

    wmma::fragment<wmma::accumulator, 16, 16, 8, float> acc[2][4];
#pragma unroll
    for (int m = 0; m < 2; m++)
#pragma unroll
        for (int n = 0; n < 4; n++) wmma::fill_fragment(acc[m][n], 0.f);

    const int ar = tid >> 1, as = (tid & 1) * 8;     // A: 128 rows x 2 halves
    const int br = tid >> 4, bs = (tid & 15) * 8;    // B: 16 rows x 16 segs

    for (int k0 = 0; k0 < K; k0 += BK) {
#pragma unroll
        for (int i = 0; i < 2; i++) {
            float4 v = *(const float4*)(Ab + (size_t)ar * lda + k0 + as + i * 4);
            float h0 = wmma::__float_to_tf32(v.x), h1 = wmma::__float_to_tf32(v.y);
            float h2 = wmma::__float_to_tf32(v.z), h3 = wmma::__float_to_tf32(v.w);
            Ah[ar][as + i * 4 + 0] = h0; Al[ar][as + i * 4 + 0] = wmma::__float_to_tf32(v.x - h0);
            Ah[ar][as + i * 4 + 1] = h1; Al[ar][as + i * 4 + 1] = wmma::__float_to_tf32(v.y - h1);
            Ah[ar][as + i * 4 + 2] = h2; Al[ar][as + i * 4 + 2] = wmma::__float_to_tf32(v.z - h2);
            Ah[ar][as + i * 4 + 3] = h3; Al[ar][as + i * 4 + 3] = wmma::__float_to_tf32(v.w - h3);
        }
#pragma unroll
        for (int i = 0; i < 2; i++) {
            float4 v = *(const float4*)(Wb + (size_t)(k0 + br) * ldw + bs + i * 4);
            float h0 = wmma::__float_to_tf32(v.x), h1 = wmma::__float_to_tf32(v.y);
            float h2 = wmma::__float_to_tf32(v.z), h3 = wmma::__float_to_tf32(v.w);
            Bh[br][bs + i * 4 + 0] = h0; Bl[br][bs + i * 4 + 0] = wmma::__float_to_tf32(v.x - h0);
            Bh[br][bs + i * 4 + 1] = h1; Bl[br][bs + i * 4 + 1] = wmma::__float_to_tf32(v.y - h1);
            Bh[br][bs + i * 4 + 2] = h2; Bl[br][bs + i * 4 + 2] = wmma::__float_to_tf32(v.z - h2);
            Bh[br][bs + i * 4 + 3] = h3; Bl[br][bs + i * 4 + 3] = wmma::__float_to_tf32(v.w - h3);
        }
        __syncthreads();
#pragma unroll
        for (int kk = 0; kk < BK; kk += 8) {
            wmma::fragment<wmma::matrix_a, 16, 16, 8, wmma::precision::tf32, wmma::row_major> ah[2], al[2];
            wmma::fragment<wmma::matrix_b, 16, 16, 8, wmma::precision::tf32, wmma::row_major> bh[4], bl[4];
#pragma unroll
            for (int m = 0; m < 2; m++) {
                wmma::load_matrix_sync(ah[m], &Ah[wr * 32 + m * 16][kk], BK + 4);
                wmma::load_matrix_sync(al[m], &Al[wr * 32 + m * 16][kk], BK + 4);
            }
#pragma unroll
            for (int n = 0; n < 4; n++) {
                wmma::load_matrix_sync(bh[n], &Bh[kk][wc * 64 + n * 16], 128 + 4);
                wmma::load_matrix_sync(bl[n], &Bl[kk][wc * 64 + n * 16], 128 + 4);
            }
#pragma unroll
            for (int m = 0; m < 2; m++)
#pragma unroll
                for (int n = 0; n < 4; n++) {
                    wmma::mma_sync(acc[m][n], ah[m], bh[n], acc[m][n]);
                    wmma::mma_sync(acc[m][n], ah[m], bl[n], acc[m][n]);
                    wmma::mma_sync(acc[m][n], al[m], bh[n], acc[m][n]);
                }
        }
        __syncthreads();
    }
#pragma unroll
    for (int m = 0; m < 2; m++)
#pragma unroll
        for (int n = 0; n < 4; n++) {
            size_t row = (size_t)(bm * 128 + wr * 32 + m * 16);
            wmma::store_matrix_sync(C + row * N + bn * 128 + wc * 64 + n * 16,
                                    acc[m][n], N, wmma::mem_row_major);
        }
}

// ---------------- cumulative grid barrier (R10-proven) ------------------------
__device__ __forceinline__ void gridbar(unsigned target) {
    __threadfence();
    __syncthreads();
    if (threadIdx.x == 0) {
        atomicAdd(&g_count, 1u);
        while (atomicAdd(&g_count, 0u) < target * (unsigned)NCTA) { __nanosleep(64); }
    }
    __syncthreads();
}

// ---------------- persistent recurrence (R10-proven layout, byte-identical) ---
// 128 CTAs x 256 threads. CTA p: nt=p&7 -> j slice [nt*32,nt*32+32);
// mt=p>>3 -> rows [mt*16,mt*16+16). Phase A owns rows {2p,2p+1}. 3 barriers.
__global__ void __launch_bounds__(256)
k_recur() {
    extern __shared__ char dsm[];
    float4* sW = (float4*)dsm;                         // [k*32 + wj], 128KB
    float*  sA = (float*)(dsm + 131072);               // 16 x 260 tile
    float*  sB = (float*)(dsm + 131072 + 16640);       // 16 x 260 tile
    __shared__ float sRed[8][8];
    __shared__ float sWts[8];

    const int p = blockIdx.x, tid = threadIdx.x;
    const int lane = tid & 31, wid = tid >> 5;
    const int nt = p & 7,  mt = p >> 3;
    const int J0 = nt * 32, R0 = mt * 16;
    const int jq = lane & 3, rr = lane >> 2;           // warp: 4 j x 8 rows
    const int wj = wid * 4 + jq;                       // 0..31 within slice
    const int jB = J0 + wj;                            // global unit index

    for (int i = tid; i < 8192; i += 256) {
        int k = i >> 5, w = i & 31;
        sW[i] = g_rk4[k * U_ + J0 + w];
    }
    __syncthreads();

    for (int t = 0; t < T_; t++) {
        const int slot = t & 7;

        // ===== Phase A: scores + softmax + hmix/cmix (rows 2p, 2p+1) ==========
        for (int r = 0; r < 2; r++) {
            const int row = 2 * p + r;
            const int dir = row >> 7, bb = row & 127;
            const int td = dir ? (T_ - 1 - t) : t;
            const size_t xrow = (size_t)(td * B_ + bb) * U_;
            const float xh = g_xh[xrow + tid], xc = g_xc[xrow + tid];
            const int base = row * U_ + tid;
            float s[8];
#pragma unroll
            for (int k = 1; k <= 4; k++) {
                int sl = (t - k) & 7;
                float th = tanhf(__ldcg(&g_QH[sl * RSZ + base]) + xh);
                s[k - 1] = th * th;
                float tc;
                if (k < 4) tc = tanhf(__ldcg(&g_QC[sl * RSZ + base]) + xc);
                else       tc = tanhf(__ldcg(&g_QC4H[sl * RSZ + base]) + xh);
                s[3 + k] = tc * tc;
            }
#pragma unroll
            for (int i = 0; i < 8; i++)
#pragma unroll
                for (int o = 16; o > 0; o >>= 1)
                    s[i] += __shfl_down_sync(0xffffffffu, s[i], o);
            if (lane == 0) {
#pragma unroll
                for (int i = 0; i < 8; i++) sRed[wid][i] = s[i];
            }
            __syncthreads();
            if (tid < 8) {
                float sum = 0.f;
#pragma unroll
                for (int ww = 0; ww < 8; ww++) sum += sRed[ww][tid];
                sWts[tid] = sqrtf(sum);
            }
            __syncthreads();
            if (tid == 0) {
#pragma unroll
                for (int g = 0; g < 8; g += 4) {
                    float a0 = sWts[g], a1 = sWts[g + 1];
                    float a2 = sWts[g + 2], a3 = sWts[g + 3];
                    float m = fmaxf(fmaxf(a0, a1), fmaxf(a2, a3));
                    float e0 = expf(a0 - m), e1 = expf(a1 - m);
                    float e2 = expf(a2 - m), e3 = expf(a3 - m);
                    float inv = 1.f / (e0 + e1 + e2 + e3);
                    sWts[g] = e0 * inv; sWts[g + 1] = e1 * inv;
                    sWts[g + 2] = e2 * inv; sWts[g + 3] = e3 * inv;
                }
            }
            __syncthreads();
            float hm = 0.f, cm = 0.f;
#pragma unroll
            for (int k = 1; k <= 4; k++) {
                int sl = (t - k) & 7;
                hm += sWts[k - 1] * __ldcg(&g_H[sl * RSZ + base]);
                cm += sWts[3 + k] * __ldcg(&g_C[sl * RSZ + base]);
            }
            g_hmix[base] = fmaxf(hm, 0.f);
            g_cmix[base] = fmaxf(cm, 0.f);
            __syncthreads();
        }
        gridbar(3u * (unsigned)t + 1u);

        // ===== Phase B: gates GEMM (weights in smem) + pointwise ==============
        for (int i = tid; i < 4096; i += 256) {
            int r = i >> 8, k = i & 255;
            sA[r * 260 + k] = __ldcg(&g_hmix[(R0 + r) * U_ + k]);
        }
        __syncthreads();
        {
            float4 acc0 = make_float4(0.f, 0.f, 0.f, 0.f);
            float4 acc1 = make_float4(0.f, 0.f, 0.f, 0.f);
#pragma unroll 4
            for (int k = 0; k < U_; k++) {
                float4 wv = sW[k * 32 + wj];
                float a0 = sA[rr * 260 + k];
                float a1 = sA[(rr + 8) * 260 + k];
                acc0.x += a0 * wv.x; acc0.y += a0 * wv.y;
                acc0.z += a0 * wv.z; acc0.w += a0 * wv.w;
                acc1.x += a1 * wv.x; acc1.y += a1 * wv.y;
                acc1.z += a1 * wv.z; acc1.w += a1 * wv.w;
            }
#pragma unroll
            for (int pr = 0; pr < 2; pr++) {
                const float4 a = pr ? acc1 : acc0;
                const int row = R0 + rr + pr * 8;
                const int dir = row >> 7, bb = row & 127;
                const int td = dir ? (T_ - 1 - t) : t;
                const size_t xrow = (size_t)(td * B_ + bb) * 1024;
                float gi = g_xg[xrow + jB]       + a.x;
                float gf = g_xg[xrow + 256 + jB] + a.y;
                float gm = g_xg[xrow + 512 + jB] + a.z;
                float go = g_xg[xrow + 768 + jB] + a.w;
                float cmv = __ldcg(&g_cmix[row * U_ + jB]);
                float c = hsig(gf) * cmv + hsig(gi) * hsig(gm);
                float h = hsig(go) * tanhf(c);
                g_H[slot * RSZ + row * U_ + jB] = h;
                g_C[slot * RSZ + row * U_ + jB] = c;
                g_outs[((size_t)bb * T_ + td) * 512 + dir * 256 + jB] = h;
            }
        }
        gridbar(3u * (unsigned)t + 2u);

        // ===== Phase C: Q products (weights via L1-resident float2 slice) =====
        for (int i = tid; i < 4096; i += 256) {
            int r = i >> 8, k = i & 255;
            sA[r * 260 + k] = __ldcg(&g_H[slot * RSZ + (R0 + r) * U_ + k]);
            sB[r * 260 + k] = __ldcg(&g_C[slot * RSZ + (R0 + r) * U_ + k]);
        }
        __syncthreads();
        {
            float aH0 = 0.f, aCH0 = 0.f, aC0 = 0.f;
            float aH1 = 0.f, aCH1 = 0.f, aC1 = 0.f;
#pragma unroll 4
            for (int k = 0; k < U_; k++) {
                float2 w = __ldg(&g_att2[k * U_ + jB]);
                float h0 = sA[rr * 260 + k],       c0 = sB[rr * 260 + k];
                float h1 = sA[(rr + 8) * 260 + k], c1 = sB[(rr + 8) * 260 + k];
                aH0  += w.x * h0;  aCH0 += w.x * c0;  aC0 += w.y * c0;
                aH1  += w.x * h1;  aCH1 += w.x * c1;  aC1 += w.y * c1;
            }
            int b0 = slot * RSZ + (R0 + rr) * U_ + jB;
            int b1 = slot * RSZ + (R0 + rr + 8) * U_ + jB;
            g_QH[b0] = aH0;  g_QC4H[b0] = aCH0;  g_QC[b0] = aC0;
            g_QH[b1] = aH1;  g_QC4H[b1] = aCH1;  g_QC[b1] = aC1;
        }
        gridbar(3u * (unsigned)t + 3u);
    }
}

// ---------------- final: ha/hb reductions + tanh epilogue ---------------------
__global__ void k_final(const float* __restrict__ att2, const float* __restrict__ att22,
                        float* __restrict__ out) {
    int r = blockIdx.x, j = threadIdx.x;
    float v1 = fmaxf(g_c1[(size_t)r * U_ + j], 0.f) * att2[j];
    float v2 = fmaxf(g_c2[(size_t)r * U_ + j], 0.f) * att22[j];
#pragma unroll
    for (int o = 16; o > 0; o >>= 1) {
        v1 += __shfl_down_sync(0xffffffffu, v1, o);
        v2 += __shfl_down_sync(0xffffffffu, v2, o);
    }
    __shared__ float s1[8], s2[8];
    int lane = j & 31, w = j >> 5;
    if (lane == 0) { s1[w] = v1; s2[w] = v2; }
    __syncthreads();
    if (j == 0) {
        float a = 0.f, bsum = 0.f;
#pragma unroll
        for (int i = 0; i < 8; i++) { a += s1[i]; bsum += s2[i]; }
        s1[0] = a; s2[0] = bsum;
    }
    __syncthreads();
    float ha = s1[0], hb = s2[0];
    size_t base = (size_t)r * 512;
    out[base + j]       = tanhf(ha * g_outs[base + j] + hb);
    out[base + 256 + j] = tanhf(ha * g_outs[base + 256 + j] + hb);
}

// ---------------- launcher ----------------------------------------------------
extern "C" void kernel_launch(void* const* d_in, const int* in_sizes, int n_in,
                              void* d_out, int out_size) {
    // ---- size-driven input mapping (robust to metadata ordering) ----
    int ix = -1, ikern = -1;
    int i262[2] = {-1, -1}, n262 = 0;
    int i196[2] = {-1, -1}, n196 = 0;
    int i256[4] = {-1, -1, -1, -1}, n256 = 0;
    for (int i = 0; i < n_in; i++) {
        int s = in_sizes[i];
        if      (s == 33554432) ix = i;
        else if (s == 524288)   ikern = i;
        else if (s == 262144) { if (n262 < 2) i262[n262++] = i; }
        else if (s == 196608) { if (n196 < 2) i196[n196++] = i; }
        else if (s == 256)    { if (n256 < 4) i256[n256++] = i; }
    }
    const bool alpha = (ix != 0);

    const float* x     = (const float*)d_in[ix];
    const float* kern  = (const float*)d_in[ikern];
    const float* rk    = (const float*)d_in[alpha ? i262[1] : i262[0]];
    const float* att1  = (const float*)d_in[alpha ? i262[0] : i262[1]];
    const float* att_h = (const float*)d_in[alpha ? i196[1] : i196[0]];
    const float* att_c = (const float*)d_in[alpha ? i196[0] : i196[1]];
    const float* att2  = (const float*)d_in[alpha ? i256[0] : i256[1]];
    const float* att22 = (const float*)d_in[alpha ? i256[1] : i256[2]];
    float* out = (float*)d_out;

    // resolve real device addresses of __device__ globals
    float *xT_p, *xg_p, *xh_p, *xc_p, *outs_p, *c1_p, *c2_p;
    cudaGetSymbolAddress((void**)&xT_p,   g_xT);
    cudaGetSymbolAddress((void**)&xg_p,   g_xg);
    cudaGetSymbolAddress((void**)&xh_p,   g_xh);
    cudaGetSymbolAddress((void**)&xc_p,   g_xc);
    cudaGetSymbolAddress((void**)&outs_p, g_outs);
    cudaGetSymbolAddress((void**)&c1_p,   g_c1);
    cudaGetSymbolAddress((void**)&c2_p,   g_c2);

    static const int kRecurSmem = 131072 + 2 * 16640;   // 164352 B
    cudaFuncSetAttribute(k_recur, cudaFuncAttributeMaxDynamicSharedMemorySize, kRecurSmem);

    k_zero<<<(RING * RSZ + 1023) / 1024, 1024>>>();
    k_permute<<<NROW, 128>>>(x);
    k_prep_rk<<<U_, U_>>>(rk);
    k_prep_att<<<U_, U_>>>(att_h, att_c);

    // precompute GEMMs on tensor cores (tf32 + staged compensation)
    k_tgemm<<<dim3(1024 / 128, NROW / 128), 256>>>(xT_p, kern,              xg_p, NROW, 1024, 512, F_, 1024);
    k_tgemm<<<dim3(256 / 128,  NROW / 128), 256>>>(xT_p, att_h + 256 * 256, xh_p, NROW, 256, 512, F_, 256);
    k_tgemm<<<dim3(256 / 128,  NROW / 128), 256>>>(xT_p, att_c + 256 * 256, xc_p, NROW, 256, 512, F_, 256);

    // persistent bidirectional recurrence (R10-proven)
    k_recur<<<NCTA, 256, kRecurSmem>>>();

    // final stage: c1 = outs@A11, c2 = x@A12, fused reduce + tanh
    k_tgemm<<<dim3(256 / 128, NROW / 128), 256>>>(outs_p, att1,             c1_p, NROW, 256, 512, 512, 256);
    k_tgemm<<<dim3(256 / 128, NROW / 128), 256>>>(x,      att1 + 512 * 256, c2_p, NROW, 256, 512, 512, 256);
    k_final<<<NROW, U_>>>(att2, att22, out);
}

// round 16
// speedup vs baseline: 1.2187x; 1.2187x over previous
#include <cuda_runtime.h>
#include <math.h>
#include <stdint.h>

#define B_   128
#define T_   512
#define F_   512
#define U_   256
#define NROW 65536        // T*B
#define NB   256          // 2*B (fwd+bwd batched)
#define RING 8
#define RSZ  (NB * U_)    // 65536
#define NCTA 128          // persistent grid <= SM count => co-resident

// ---------------- scratch (__device__ globals; no allocation allowed) ---------
__device__ float g_xT [(size_t)NROW * F_];
__device__ float g_xg [(size_t)NROW * 1024];
__device__ float g_xh [(size_t)NROW * U_];
__device__ float g_xc [(size_t)NROW * U_];
__device__ float g_outs[(size_t)NROW * 512];
__device__ float g_c1 [(size_t)NROW * U_];
__device__ float g_c2 [(size_t)NROW * U_];
__device__ float g_H   [RING * RSZ];
__device__ float g_C   [RING * RSZ];
__device__ float g_QH  [RING * RSZ];     // h_k @ Wh_state
__device__ float g_QC  [RING * RSZ];     // c_k @ Wc_state
__device__ float g_QC4H[RING * RSZ];     // c_k @ Wh_state (4th c-slot uses Wh)
__device__ float g_spart[NB * 8 * 8];    // score partials [row][nt][8]
__device__ float4 g_rk4 [U_ * U_];       // rk: [k][j] -> (i,f,m,o)
__device__ float2 g_att2[U_ * U_];       // [k][j] -> (Wh_state, Wc_state)
__device__ unsigned g_count;             // cumulative barrier counter

__device__ __forceinline__ float hsig(float x) {
    return fminf(fmaxf(0.2f * x + 0.5f, 0.f), 1.f);
}
__device__ __forceinline__ float t2(float x) { float t = tanhf(x); return t * t; }

// ---------------- per-launch init ---------------------------------------------
__global__ void k_zero() {
    int i = blockIdx.x * blockDim.x + threadIdx.x;
    if (i < RING * RSZ) {
        g_H[i] = 0.f; g_C[i] = 0.f;
        g_QH[i] = 0.f; g_QC[i] = 0.f; g_QC4H[i] = 0.f;
    }
    if (i < NB * 64) g_spart[i] = 0.f;
    if (i == 0) g_count = 0u;
}

// ---------------- permute x (b,t,f) -> (t,b,f) --------------------------------
__global__ void k_permute(const float* __restrict__ x) {
    int r = blockIdx.x;                 // r = t*128 + b
    int t = r >> 7, b = r & 127;
    const float4* src = (const float4*)(x + ((size_t)b * T_ + t) * F_);
    float4* dst = (float4*)(g_xT + (size_t)r * F_);
    dst[threadIdx.x] = src[threadIdx.x];
}

// ---------------- weight prep --------------------------------------------------
__global__ void k_prep_rk(const float* __restrict__ rk) {
    int k = blockIdx.x, j = threadIdx.x;
    g_rk4[k * U_ + j] = make_float4(rk[k * 1024 + j],
                                    rk[k * 1024 + 256 + j],
                                    rk[k * 1024 + 512 + j],
                                    rk[k * 1024 + 768 + j]);
}
__global__ void k_prep_att(const float* __restrict__ att_h, const float* __restrict__ att_c) {
    int k = blockIdx.x, j = threadIdx.x;
    g_att2[k * U_ + j] = make_float2(att_h[k * U_ + j], att_c[k * U_ + j]);
}

// ---------------- t=0 score partials (states are zero => scores from x only) --
__global__ void k_initss() {
    __shared__ float red[8][2];
    int row = blockIdx.x, j = threadIdx.x;
    int dir = row >> 7, bb = row & 127;
    int td0 = dir ? (T_ - 1) : 0;
    size_t xb = (size_t)(td0 * B_ + bb) * U_ + j;
    float sh = t2(g_xh[xb]);
    float sc = t2(g_xc[xb]);
#pragma unroll
    for (int o = 16; o > 0; o >>= 1) {
        sh += __shfl_down_sync(0xffffffffu, sh, o);
        sc += __shfl_down_sync(0xffffffffu, sc, o);
    }
    int lane = j & 31, w = j >> 5;
    if (lane == 0) { red[w][0] = sh; red[w][1] = sc; }
    __syncthreads();
    if (j == 0) {
        float Sh = 0.f, Sc = 0.f;
#pragma unroll
        for (int ww = 0; ww < 8; ww++) { Sh += red[ww][0]; Sc += red[ww][1]; }
        red[0][0] = Sh; red[0][1] = Sc;
    }
    __syncthreads();
    float Sh = red[0][0], Sc = red[0][1];
    if (j < 64) {
        int q = j >> 3, st = j & 7;
        float v = 0.f;
        if (q == 0) v = (st < 4 || st == 7) ? Sh : Sc;   // 4th c-score uses Wh -> xh
        g_spart[(row * 8 + q) * 8 + st] = v;
    }
}

// ---------------- classic 128x128x8 SGEMM, 8x8 microtile (validated) ----------
__global__ void k_sgemm(const float* __restrict__ A, const float* __restrict__ W,
                        float* __restrict__ C, int M, int N, int K, int lda, int ldw) {
    __shared__ float As[8][128];
    __shared__ float Bs[8][128];
    int tid = threadIdx.x;
    int bm = blockIdx.y, bn = blockIdx.x;
    const float* Ablk = A + (size_t)bm * 128 * lda;
    const float* Wblk = W + bn * 128;
    float acc[8][8];
#pragma unroll
    for (int i = 0; i < 8; i++)
#pragma unroll
        for (int j = 0; j < 8; j++) acc[i][j] = 0.f;
    int aRow = tid >> 1, aCol = (tid & 1) * 4;
    int bRow = tid >> 5, bCol = (tid & 31) * 4;
    int tx = tid & 15, ty = tid >> 4;
    for (int k0 = 0; k0 < K; k0 += 8) {
        float4 av = *(const float4*)(Ablk + (size_t)aRow * lda + k0 + aCol);
        As[aCol + 0][aRow] = av.x; As[aCol + 1][aRow] = av.y;
        As[aCol + 2][aRow] = av.z; As[aCol + 3][aRow] = av.w;
        float4 bv = *(const float4*)(Wblk + (size_t)(k0 + bRow) * ldw + bCol);
        *(float4*)&Bs[bRow][bCol] = bv;
        __syncthreads();
#pragma unroll
        for (int kk = 0; kk < 8; kk++) {
            float4 a0 = *(const float4*)&As[kk][ty * 8];
            float4 a1 = *(const float4*)&As[kk][ty * 8 + 4];
            float4 b0 = *(const float4*)&Bs[kk][tx * 8];
            float4 b1 = *(const float4*)&Bs[kk][tx * 8 + 4];
            float ra[8] = {a0.x, a0.y, a0.z, a0.w, a1.x, a1.y, a1.z, a1.w};
            float rb[8] = {b0.x, b0.y, b0.z, b0.w, b1.x, b1.y, b1.z, b1.w};
#pragma unroll
            for (int i = 0; i < 8; i++)
#pragma unroll
                for (int j = 0; j < 8; j++) acc[i][j] += ra[i] * rb[j];
        }
        __syncthreads();
    }
#pragma unroll
    for (int i = 0; i < 8; i++) {
        size_t row = (size_t)(bm * 128 + ty * 8 + i);
        *(float4*)(C + row * N + bn * 128 + tx * 8)     =
            make_float4(acc[i][0], acc[i][1], acc[i][2], acc[i][3]);
        *(float4*)(C + row * N + bn * 128 + tx * 8 + 4) =
            make_float4(acc[i][4], acc[i][5], acc[i][6], acc[i][7]);
    }
}

// ---------------- cumulative grid barrier (R10-proven) ------------------------
__device__ __forceinline__ void gridbar(unsigned target) {
    __threadfence();
    __syncthreads();
    if (threadIdx.x == 0) {
        atomicAdd(&g_count, 1u);
        while (atomicAdd(&g_count, 0u) < target * (unsigned)NCTA) { __nanosleep(64); }
    }
    __syncthreads();
}

// ---------------- persistent recurrence: 2 phases / step, 2 barriers ----------
// 128 CTAs x 256 threads. CTA p: nt=p&7 -> j slice [nt*32,nt*32+32);
// mt=p>>3 -> rows [mt*16,mt*16+16). Scores for t+1 pipelined into Phase C.
__global__ void __launch_bounds__(256)
k_recur() {
    extern __shared__ char dsm[];
    float4* sW = (float4*)dsm;                         // [k*32 + wj], 128KB
    float*  sA = (float*)(dsm + 131072);               // 16 x 260 tile
    float*  sB = (float*)(dsm + 131072 + 16640);       // 16 x 260 tile
    __shared__ float sWts[16][8];
    __shared__ float sSw[8][16][8];                    // per-warp score partials

    const int p = blockIdx.x, tid = threadIdx.x;
    const int lane = tid & 31, wid = tid >> 5;
    const int nt = p & 7,  mt = p >> 3;
    const int J0 = nt * 32, R0 = mt * 16;
    const int jq = lane & 3, rr = lane >> 2;           // warp: 4 j x 8 rows
    const int wj = wid * 4 + jq;                       // 0..31 within slice
    const int jB = J0 + wj;                            // global unit index

    // one-time: rk4 slice -> smem (reused all 512 steps)
    for (int i = tid; i < 8192; i += 256) {
        int k = i >> 5, w = i & 31;
        sW[i] = g_rk4[k * U_ + J0 + w];
    }
    __syncthreads();

    for (int t = 0; t < T_; t++) {
        const int slot = t & 7;

        // ===== Phase BG: weights + hmix + gates GEMM + pointwise ==============
        if (tid < 128) {
            int r = tid >> 3, st = tid & 7;
            float s = 0.f;
#pragma unroll
            for (int q = 0; q < 8; q++)
                s += __ldcg(&g_spart[((R0 + r) * 8 + q) * 8 + st]);
            sWts[r][st] = sqrtf(s);
        }
        __syncthreads();
        if (tid < 32) {
            int r = tid >> 1, grp = (tid & 1) * 4;
            float a0 = sWts[r][grp], a1 = sWts[r][grp + 1];
            float a2 = sWts[r][grp + 2], a3 = sWts[r][grp + 3];
            float m = fmaxf(fmaxf(a0, a1), fmaxf(a2, a3));
            float e0 = expf(a0 - m), e1 = expf(a1 - m);
            float e2 = expf(a2 - m), e3 = expf(a3 - m);
            float inv = 1.f / (e0 + e1 + e2 + e3);
            sWts[r][grp] = e0 * inv; sWts[r][grp + 1] = e1 * inv;
            sWts[r][grp + 2] = e2 * inv; sWts[r][grp + 3] = e3 * inv;
        }
        __syncthreads();

        // hmix rows (16 x 256) into sA
        for (int r = 0; r < 16; r++) {
            float hm = 0.f;
#pragma unroll
            for (int k = 1; k <= 4; k++)
                hm += sWts[r][k - 1] * __ldcg(&g_H[((t - k) & 7) * RSZ + (R0 + r) * U_ + tid]);
            sA[r * 260 + tid] = fmaxf(hm, 0.f);
        }
        __syncthreads();
        {
            float4 acc0 = make_float4(0.f, 0.f, 0.f, 0.f);
            float4 acc1 = make_float4(0.f, 0.f, 0.f, 0.f);
#pragma unroll 4
            for (int k = 0; k < U_; k++) {
                float4 wv = sW[k * 32 + wj];
                float a0 = sA[rr * 260 + k];
                float a1 = sA[(rr + 8) * 260 + k];
                acc0.x += a0 * wv.x; acc0.y += a0 * wv.y;
                acc0.z += a0 * wv.z; acc0.w += a0 * wv.w;
                acc1.x += a1 * wv.x; acc1.y += a1 * wv.y;
                acc1.z += a1 * wv.z; acc1.w += a1 * wv.w;
            }
#pragma unroll
            for (int pr = 0; pr < 2; pr++) {
                const float4 a = pr ? acc1 : acc0;
                const int lr = rr + pr * 8;
                const int row = R0 + lr;
                const int dir = row >> 7, bb = row & 127;
                const int td = dir ? (T_ - 1 - t) : t;
                const size_t xrow = (size_t)(td * B_ + bb) * 1024;
                float gi = g_xg[xrow + jB]       + a.x;
                float gf = g_xg[xrow + 256 + jB] + a.y;
                float gm = g_xg[xrow + 512 + jB] + a.z;
                float go = g_xg[xrow + 768 + jB] + a.w;
                float cm = 0.f;
#pragma unroll
                for (int k = 1; k <= 4; k++)
                    cm += sWts[lr][3 + k] * __ldcg(&g_C[((t - k) & 7) * RSZ + row * U_ + jB]);
                cm = fmaxf(cm, 0.f);
                float c = hsig(gf) * cm + hsig(gi) * hsig(gm);
                float h = hsig(go) * tanhf(c);
                g_H[slot * RSZ + row * U_ + jB] = h;
                g_C[slot * RSZ + row * U_ + jB] = c;
                g_outs[((size_t)bb * T_ + td) * 512 + dir * 256 + jB] = h;
            }
        }
        gridbar(2u * (unsigned)t + 1u);

        // ===== Phase CQ: Q products + pipelined scores for step t+1 ===========
        for (int i = tid; i < 4096; i += 256) {
            int r = i >> 8, k = i & 255;
            sA[r * 260 + k] = __ldcg(&g_H[slot * RSZ + (R0 + r) * U_ + k]);
            sB[r * 260 + k] = __ldcg(&g_C[slot * RSZ + (R0 + r) * U_ + k]);
        }
        __syncthreads();
        {
            float aH0 = 0.f, aCH0 = 0.f, aC0 = 0.f;
            float aH1 = 0.f, aCH1 = 0.f, aC1 = 0.f;
#pragma unroll 4
            for (int k = 0; k < U_; k++) {
                float2 w = __ldg(&g_att2[k * U_ + jB]);
                float h0 = sA[rr * 260 + k],       c0 = sB[rr * 260 + k];
                float h1 = sA[(rr + 8) * 260 + k], c1 = sB[(rr + 8) * 260 + k];
                aH0  += w.x * h0;  aCH0 += w.x * c0;  aC0 += w.y * c0;
                aH1  += w.x * h1;  aCH1 += w.x * c1;  aC1 += w.y * c1;
            }
            int b0 = slot * RSZ + (R0 + rr) * U_ + jB;
            int b1 = slot * RSZ + (R0 + rr + 8) * U_ + jB;
            g_QH[b0] = aH0;  g_QC4H[b0] = aCH0;  g_QC[b0] = aC0;
            g_QH[b1] = aH1;  g_QC4H[b1] = aCH1;  g_QC[b1] = aC1;

            // ---- scores for step t+1: k=1 fresh (registers), k=2..4 from ring
            if (t < T_ - 1) {
                const int s1 = (t - 1) & 7, s2 = (t - 2) & 7, s3 = (t - 3) & 7;
#pragma unroll
                for (int pr = 0; pr < 2; pr++) {
                    const int lr = rr + pr * 8;
                    const int row = R0 + lr;
                    const int dir = row >> 7, bb = row & 127;
                    const int td1 = dir ? (T_ - 2 - t) : (t + 1);
                    const size_t xb = (size_t)(td1 * B_ + bb) * U_ + jB;
                    const float xh = g_xh[xb], xc = g_xc[xb];
                    const int ro = row * U_ + jB;
                    float v[8];
                    v[0] = t2((pr ? aH1 : aH0) + xh);
                    v[1] = t2(__ldcg(&g_QH[s1 * RSZ + ro]) + xh);
                    v[2] = t2(__ldcg(&g_QH[s2 * RSZ + ro]) + xh);
                    v[3] = t2(__ldcg(&g_QH[s3 * RSZ + ro]) + xh);
                    v[4] = t2((pr ? aC1 : aC0) + xc);
                    v[5] = t2(__ldcg(&g_QC[s1 * RSZ + ro]) + xc);
                    v[6] = t2(__ldcg(&g_QC[s2 * RSZ + ro]) + xc);
                    v[7] = t2(__ldcg(&g_QC4H[s3 * RSZ + ro]) + xh);  // 4th c uses Wh
#pragma unroll
                    for (int i = 0; i < 8; i++) {
                        v[i] += __shfl_down_sync(0xffffffffu, v[i], 2, 4);
                        v[i] += __shfl_down_sync(0xffffffffu, v[i], 1, 4);
                    }
                    if (jq == 0) {
#pragma unroll
                        for (int i = 0; i < 8; i++) sSw[wid][lr][i] = v[i];
                    }
                }
            }
        }
        __syncthreads();
        if (t < T_ - 1 && tid < 128) {
            int r = tid >> 3, st = tid & 7;
            float s = 0.f;
#pragma unroll
            for (int w = 0; w < 8; w++) s += sSw[w][r][st];
            g_spart[((R0 + r) * 8 + nt) * 8 + st] = s;
        }
        gridbar(2u * (unsigned)t + 2u);
    }
}

// ---------------- final: ha/hb reductions + tanh epilogue ---------------------
__global__ void k_final(const float* __restrict__ att2, const float* __restrict__ att22,
                        float* __restrict__ out) {
    int r = blockIdx.x, j = threadIdx.x;
    float v1 = fmaxf(g_c1[(size_t)r * U_ + j], 0.f) * att2[j];
    float v2 = fmaxf(g_c2[(size_t)r * U_ + j], 0.f) * att22[j];
#pragma unroll
    for (int o = 16; o > 0; o >>= 1) {
        v1 += __shfl_down_sync(0xffffffffu, v1, o);
        v2 += __shfl_down_sync(0xffffffffu, v2, o);
    }
    __shared__ float s1[8], s2[8];
    int lane = j & 31, w = j >> 5;
    if (lane == 0) { s1[w] = v1; s2[w] = v2; }
    __syncthreads();
    if (j == 0) {
        float a = 0.f, bsum = 0.f;
#pragma unroll
        for (int i = 0; i < 8; i++) { a += s1[i]; bsum += s2[i]; }
        s1[0] = a; s2[0] = bsum;
    }
    __syncthreads();
    float ha = s1[0], hb = s2[0];
    size_t base = (size_t)r * 512;
    out[base + j]       = tanhf(ha * g_outs[base + j] + hb);
    out[base + 256 + j] = tanhf(ha * g_outs[base + 256 + j] + hb);
}

// ---------------- launcher ----------------------------------------------------
extern "C" void kernel_launch(void* const* d_in, const int* in_sizes, int n_in,
                              void* d_out, int out_size) {
    // ---- size-driven input mapping (robust to metadata ordering) ----
    int ix = -1, ikern = -1;
    int i262[2] = {-1, -1}, n262 = 0;
    int i196[2] = {-1, -1}, n196 = 0;
    int i256[4] = {-1, -1, -1, -1}, n256 = 0;
    for (int i = 0; i < n_in; i++) {
        int s = in_sizes[i];
        if      (s == 33554432) ix = i;
        else if (s == 524288)   ikern = i;
        else if (s == 262144) { if (n262 < 2) i262[n262++] = i; }
        else if (s == 196608) { if (n196 < 2) i196[n196++] = i; }
        else if (s == 256)    { if (n256 < 4) i256[n256++] = i; }
    }
    const bool alpha = (ix != 0);

    const float* x     = (const float*)d_in[ix];
    const float* kern  = (const float*)d_in[ikern];
    const float* rk    = (const float*)d_in[alpha ? i262[1] : i262[0]];
    const float* att1  = (const float*)d_in[alpha ? i262[0] : i262[1]];
    const float* att_h = (const float*)d_in[alpha ? i196[1] : i196[0]];
    const float* att_c = (const float*)d_in[alpha ? i196[0] : i196[1]];
    const float* att2  = (const float*)d_in[alpha ? i256[0] : i256[1]];
    const float* att22 = (const float*)d_in[alpha ? i256[1] : i256[2]];
    float* out = (float*)d_out;

    // resolve real device addresses of __device__ globals
    float *xT_p, *xg_p, *xh_p, *xc_p, *outs_p, *c1_p, *c2_p;
    cudaGetSymbolAddress((void**)&xT_p,   g_xT);
    cudaGetSymbolAddress((void**)&xg_p,   g_xg);
    cudaGetSymbolAddress((void**)&xh_p,   g_xh);
    cudaGetSymbolAddress((void**)&xc_p,   g_xc);
    cudaGetSymbolAddress((void**)&outs_p, g_outs);
    cudaGetSymbolAddress((void**)&c1_p,   g_c1);
    cudaGetSymbolAddress((void**)&c2_p,   g_c2);

    static const int kRecurSmem = 131072 + 2 * 16640;   // 164352 B
    cudaFuncSetAttribute(k_recur, cudaFuncAttributeMaxDynamicSharedMemorySize, kRecurSmem);

    k_zero<<<(RING * RSZ + 1023) / 1024, 1024>>>();
    k_permute<<<NROW, 128>>>(x);
    k_prep_rk<<<U_, U_>>>(rk);
    k_prep_att<<<U_, U_>>>(att_h, att_c);

    // precompute GEMMs: xg = xT@kernel, xh/xc = xT @ (x-halves of Wh/Wc)
    k_sgemm<<<dim3(1024 / 128, NROW / 128), 256>>>(xT_p, kern,              xg_p, NROW, 1024, 512, F_, 1024);
    k_sgemm<<<dim3(256 / 128,  NROW / 128), 256>>>(xT_p, att_h + 256 * 256, xh_p, NROW, 256, 512, F_, 256);
    k_sgemm<<<dim3(256 / 128,  NROW / 128), 256>>>(xT_p, att_c + 256 * 256, xc_p, NROW, 256, 512, F_, 256);

    // t=0 score partials (states zero => scores from x parts only)
    k_initss<<<NB, U_>>>();

    // persistent bidirectional recurrence (2 barriers/step, pipelined scores)
    k_recur<<<NCTA, 256, kRecurSmem>>>();

    // final stage: c1 = outs@A11, c2 = x@A12, fused reduce + tanh
    k_sgemm<<<dim3(256 / 128, NROW / 128), 256>>>(outs_p, att1,             c1_p, NROW, 256, 512, 512, 256);
    k_sgemm<<<dim3(256 / 128, NROW / 128), 256>>>(x,      att1 + 512 * 256, c2_p, NROW, 256, 512, 512, 256);
    k_final<<<NROW, U_>>>(att2, att22, out);
}